// round 12
// baseline (speedup 1.0000x reference)
#include <cuda_runtime.h>
#include <cstdint>

#define NB 16
#define NS 4
#define NK 11
#define NBS (NB * NS)         // 64
#define NBSK (NB * NS * NK)   // 704
#define NTHR 128

#define NSTAGE 4
#define CHUNK_F4 256          // 256 float4 = 4KB per stream per chunk
#define CHUNK_B  4096
#define NCHUNK   16           // 4096 f4 per map / 256

// Scratch: per-(b,s,k) partials + per-(b,s) arrival counters (graph-safe:
// counters reset by finisher each launch).
__device__ float    g_part[2 * NBSK];
__device__ unsigned g_cnt[NBS];

__device__ __forceinline__ unsigned atom_add_release_gpu(unsigned* p, unsigned v)
{
    unsigned old;
    asm volatile("atom.release.gpu.global.add.u32 %0, [%1], %2;"
                 : "=r"(old) : "l"(p), "r"(v) : "memory");
    return old;
}

#define MBAR_INIT(a, c) \
    asm volatile("mbarrier.init.shared.b64 [%0], %1;" :: "r"(a), "r"(c) : "memory")
#define MBAR_EXPECT_TX(a, b) \
    asm volatile("mbarrier.arrive.expect_tx.shared.b64 _, [%0], %1;" :: "r"(a), "r"(b) : "memory")
#define MBAR_ARRIVE(a) \
    asm volatile("mbarrier.arrive.shared.b64 _, [%0];" :: "r"(a) : "memory")
#define MBAR_INVAL(a) \
    asm volatile("mbarrier.inval.shared.b64 [%0];" :: "r"(a) : "memory")
#define MBAR_WAIT(a, par) do {                                              \
    uint32_t _done = 0;                                                     \
    while (!_done) {                                                        \
        asm volatile("{\n\t.reg .pred p;\n\t"                               \
                     "mbarrier.try_wait.parity.shared.b64 p, [%1], %2;\n\t" \
                     "selp.b32 %0, 1, 0, p;\n\t}"                           \
                     : "=r"(_done) : "r"(a), "r"(par) : "memory");          \
    }                                                                       \
} while (0)
#define BULK_G2S(dst, src, bytes, mbar)                                            \
    asm volatile("cp.async.bulk.shared::cta.global.mbarrier::complete_tx::bytes "  \
                 "[%0], [%1], %2, [%3];"                                           \
                 :: "r"(dst), "l"(src), "r"(bytes), "r"(mbar) : "memory")

// 704 CTAs x 128 thr, 5 CTAs/SM => whole grid one resident wave.
// TMA(bulk)->smem pipeline: in-flight bytes live in SMEM, not registers, so
// MLP is decoupled from register pressure (~24KB in flight per CTA).
__global__ void __launch_bounds__(NTHR, 5)
keypoint_main_kernel(const float* __restrict__ cp,     // (16,4,22,128,128)
                     const float* __restrict__ heat,   // (16,11,128,128)
                     const float* __restrict__ lab,    // (16,11,11)
                     float* __restrict__ out)          // 128 floats
{
    __shared__ __align__(128) float4 sh_h[NSTAGE][CHUNK_F4];
    __shared__ __align__(128) float4 sh_g[NSTAGE][CHUNK_F4];
    __shared__ __align__(8) unsigned long long mb_full[NSTAGE];
    __shared__ __align__(8) unsigned long long mb_empty[NSTAGE];

    const int bsk = blockIdx.x;          // 0..703
    const int k   = bsk % NK;
    const int bs  = bsk / NK;            // b*4+s
    const int b   = bs >> 2;
    const int t   = threadIdx.x;         // 0..127

    const float* __restrict__ hsrc = cp   + ((size_t)(bs * 22 + k) << 14);
    const float* __restrict__ gsrc = heat + ((size_t)(b * NK + k) << 14);

    uint32_t full_a[NSTAGE], empty_a[NSTAGE], sh_h_a[NSTAGE], sh_g_a[NSTAGE];
    #pragma unroll
    for (int s = 0; s < NSTAGE; s++) {
        full_a[s]  = (uint32_t)__cvta_generic_to_shared(&mb_full[s]);
        empty_a[s] = (uint32_t)__cvta_generic_to_shared(&mb_empty[s]);
        sh_h_a[s]  = (uint32_t)__cvta_generic_to_shared(&sh_h[s][0]);
        sh_g_a[s]  = (uint32_t)__cvta_generic_to_shared(&sh_g[s][0]);
    }

    if (t == 0) {
        #pragma unroll
        for (int s = 0; s < NSTAGE; s++) {
            MBAR_INIT(full_a[s], 1);
            MBAR_INIT(empty_a[s], NTHR);
        }
    }
    __syncthreads();

    // Prologue: fill all 4 stages (chunks 0..3).
    if (t == 0) {
        #pragma unroll
        for (int c = 0; c < NSTAGE; c++) {
            MBAR_EXPECT_TX(full_a[c], 2 * CHUNK_B);
            BULK_G2S(sh_h_a[c], (const void*)(hsrc + c * (CHUNK_F4 * 4)),
                     CHUNK_B, full_a[c]);
            BULK_G2S(sh_g_a[c], (const void*)(gsrc + c * (CHUNK_F4 * 4)),
                     CHUNK_B, full_a[c]);
        }
    }

    float s0 = 0.0f, s1 = 0.0f;
    float mx = -__int_as_float(0x7f800000); // -inf
    int   mi = 0;

    #pragma unroll
    for (int c = 0; c < NCHUNK; c++) {
        const int st = c & (NSTAGE - 1);
        const int r  = c >> 2;               // round
        MBAR_WAIT(full_a[st], r & 1);

        // consume: 2 float4 per thread per stream
        const float4* hp = &sh_h[st][0];
        const float4* gp = &sh_g[st][0];
        #pragma unroll
        for (int u = 0; u < 2; u++) {
            const int v = t + u * NTHR;      // [0,256)
            const float4 h = hp[v];
            const float4 g = gp[v];
            const int base = ((c << 8) + v) << 2;  // global element index
            float d0 = h.x - g.x, d1 = h.y - g.y;
            float d2 = h.z - g.z, d3 = h.w - g.w;
            s0 = fmaf(d0, d0, s0);
            s1 = fmaf(d1, d1, s1);
            s0 = fmaf(d2, d2, s0);
            s1 = fmaf(d3, d3, s1);
            // ascending index -> strict > keeps first occurrence
            if (h.x > mx) { mx = h.x; mi = base; }
            if (h.y > mx) { mx = h.y; mi = base + 1; }
            if (h.z > mx) { mx = h.z; mi = base + 2; }
            if (h.w > mx) { mx = h.w; mi = base + 3; }
        }
        MBAR_ARRIVE(empty_a[st]);

        // refill this stage with chunk c+4
        if (t == 0 && c + NSTAGE < NCHUNK) {
            const int c2 = c + NSTAGE;
            const int r2 = c2 >> 2;
            MBAR_WAIT(empty_a[st], (r2 - 1) & 1);
            MBAR_EXPECT_TX(full_a[st], 2 * CHUNK_B);
            BULK_G2S(sh_h_a[st], (const void*)(hsrc + c2 * (CHUNK_F4 * 4)),
                     CHUNK_B, full_a[st]);
            BULK_G2S(sh_g_a[st], (const void*)(gsrc + c2 * (CHUNK_F4 * 4)),
                     CHUNK_B, full_a[st]);
        }
    }
    float sum = s0 + s1;

    // Warp reduce (sum, argmax with lowest-index tiebreak)
    #pragma unroll
    for (int off = 16; off > 0; off >>= 1) {
        float osum = __shfl_down_sync(0xffffffffu, sum, off);
        float omx  = __shfl_down_sync(0xffffffffu, mx,  off);
        int   omi  = __shfl_down_sync(0xffffffffu, mi,  off);
        sum += osum;
        if (omx > mx || (omx == mx && omi < mi)) { mx = omx; mi = omi; }
    }

    __shared__ float ssum[4];
    __shared__ float smx[4];
    __shared__ int   smi[4];
    const int w = t >> 5, l = t & 31;
    if (l == 0) { ssum[w] = sum; smx[w] = mx; smi[w] = mi; }
    __syncthreads();

    if (t == 0) {
        #pragma unroll
        for (int w2 = 1; w2 < 4; w2++) {
            sum += ssum[w2];
            if (smx[w2] > mx || (smx[w2] == mx && smi[w2] < mi)) {
                mx = smx[w2]; mi = smi[w2];
            }
        }

        // ---- label-loss term for this (b,s,k) ----
        const float* __restrict__ lp =
            cp + ((size_t)(bs * 22 + NK + k) << 14);     // lb map, first 9 used
        const float* __restrict__ lb = lab + (size_t)(b * NK + k) * 11;

        const float gx = lb[9];
        const float gy = lb[10];
        const bool valid = (gx > 0.0f) && (gy > 0.0f) &&
                           (gx < 128.0f) && (gy < 128.0f);

        const float xf = (float)(mi >> 7);    // index // 128
        const float yf = (float)(mi & 127);   // index % 128

        const float dx = gx + lb[7] - xf - lp[7];
        const float dy = gy + lb[8] - yf - lp[8];
        const float xy_loss = dx * dx + dy * dy;

        const float c = 1.0f - mx;
        const float conf_loss = c * c;

        float cls = 0.0f;
        #pragma unroll
        for (int j = 0; j < 7; j++) {
            const float d = lp[j] - lb[j];
            cls = fmaf(d, d, cls);
        }

        __stcg(&g_part[bsk], sum);
        __stcg(&g_part[NBSK + bsk],
               valid ? (cls + xy_loss + conf_loss) : 0.0f);

        // Release-only ordering; reader uses ld.cg (L1-bypass).
        const unsigned prev = atom_add_release_gpu(&g_cnt[bs], 1u);
        if (prev == NK - 1) {
            g_cnt[bs] = 0;               // reset for next graph replay
            float hsum = 0.0f, lsum = 0.0f;
            #pragma unroll
            for (int kk = 0; kk < NK; kk++) {
                hsum += __ldcg(&g_part[bs * NK + kk]);
                lsum += __ldcg(&g_part[NBSK + bs * NK + kk]);
            }
            out[bs]      = hsum;         // heat_loss (16,4)
            out[64 + bs] = lsum;         // label_loss (16,4)
        }

        // Invalidate barriers so re-init on the next graph replay is legal.
        #pragma unroll
        for (int s = 0; s < NSTAGE; s++) {
            MBAR_INVAL(full_a[s]);
            MBAR_INVAL(empty_a[s]);
        }
    }
}

extern "C" void kernel_launch(void* const* d_in, const int* in_sizes, int n_in,
                              void* d_out, int out_size)
{
    const float* cp   = (const float*)d_in[0]; // combined_preds
    const float* heat = (const float*)d_in[1]; // heatmaps
    const float* lab  = (const float*)d_in[2]; // labels
    float* out = (float*)d_out;

    keypoint_main_kernel<<<NBSK, NTHR>>>(cp, heat, lab, out);
}